// round 14
// baseline (speedup 1.0000x reference)
#include <cuda_runtime.h>
#include <math.h>
#include <mma.h>
using namespace nvcuda;

// ---- problem dims ----
#define NSAMP 10000
#define LTOK  32
#define DD    300
#define HH    300
#define BB    256
#define NMX   128
#define ITERS 50

// ---- scratch ----
__device__ float g_enc [NSAMP*DD];
__device__ float g_h1  [NSAMP*HH];
__device__ float g_henc[NSAMP*HH];
__device__ float g_henct[NSAMP*HH];
__device__ float g_Hc  [2*NSAMP*HH];
__device__ float g_Wr  [4*HH*HH];
__device__ float g_invh[NSAMP];
__device__ float g_Pmat[BB*NMX*NMX];
__device__ float g_cr  [BB*HH];
__device__ float g_cc  [BB*HH];

// ---- streams/events (static init, pre-checkpoint) ----
struct HxStreams {
    cudaStream_t sB;
    cudaEvent_t eHenc, eHc;
    HxStreams() {
        cudaStreamCreateWithFlags(&sB, cudaStreamNonBlocking);
        cudaEventCreateWithFlags(&eHenc, cudaEventDisableTiming);
        cudaEventCreateWithFlags(&eHc,   cudaEventDisableTiming);
    }
};
static HxStreams g_hx;

// ---- cp.async helpers ----
__device__ __forceinline__ void cpa16(unsigned int dst, const void* src) {
    asm volatile("cp.async.ca.shared.global [%0], [%1], 16;" :: "r"(dst), "l"(src));
}
__device__ __forceinline__ void cpa_commit() {
    asm volatile("cp.async.commit_group;");
}
template<int NN> __device__ __forceinline__ void cpa_wait() {
    asm volatile("cp.async.wait_group %0;" :: "n"(NN));
}

__device__ __forceinline__ float tf32r(float x) { return wmma::__float_to_tf32(x); }
__device__ __forceinline__ float4 tf32r4(float4 v) {
    v.x = tf32r(v.x); v.y = tf32r(v.y); v.z = tf32r(v.z); v.w = tf32r(v.w);
    return v;
}

// ============================================================
// 0) pre-round weights to tf32 (RN) into scratch
// ============================================================
__global__ void k_roundw(const float* __restrict__ W1, const float* __restrict__ W2,
                         const float* __restrict__ Wc, float* __restrict__ Wr) {
    int i = blockIdx.x * 256 + threadIdx.x;
    if (i < HH*HH)   Wr[i]           = tf32r(W1[i]);
    if (i < HH*HH)   Wr[HH*HH + i]   = tf32r(W2[i]);
    if (i < 2*HH*HH) Wr[2*HH*HH + i] = tf32r(Wc[i]);
}

// ============================================================
// 1) embedding + masked mean pool (output rounded to tf32)
// ============================================================
__global__ void k_embed(const int* __restrict__ data,
                        const float* __restrict__ emb,
                        float* __restrict__ enc) {
    int s = blockIdx.x;
    int t = threadIdx.x;            // 320 threads
    __shared__ int toks[LTOK];
    if (t < LTOK) toks[t] = data[s*LTOK + t];
    __syncthreads();
    int cnt = 0;
#pragma unroll
    for (int l = 0; l < LTOK; l++) cnt += (toks[l] != 0);
    float inv = 1.0f / (float)(cnt > 0 ? cnt : 1);
    if (t < DD) {
        float acc = 0.f;
#pragma unroll
        for (int l = 0; l < LTOK; l++) {
            int tok = toks[l];
            if (tok != 0) acc += emb[tok*DD + t];
        }
        enc[s*DD + t] = tf32r(acc * inv);
    }
}

// ============================================================
// 2) WMMA tf32 GEMM (R11 config): 128x128, BK=16, 256 thr, 8 warps
// ============================================================
#define SA   20
#define SB   132
#define SB2  164
#define ASTG (128*SA)        // 2560
#define BSTG (16*SB)         // 2112
#define BSTG2 (16*SB2)       // 2624
#define WG2_SMEM (2*(ASTG+BSTG)*4)   // 37376

template<bool RELU>
__global__ void __launch_bounds__(256, 2)
k_wgemm2(const float* __restrict__ A, const float* __restrict__ B,
         const float* __restrict__ bias, float* __restrict__ C, float* __restrict__ C2,
         int M, int N, int K, long bStride, long cStride, int round_mask) {
    B += (long)blockIdx.z * bStride;
    C += (long)blockIdx.z * cStride;
    bool rnd = (round_mask >> blockIdx.z) & 1;
    extern __shared__ float sm[];
    unsigned int smb = (unsigned int)__cvta_generic_to_shared(sm);
    int t = threadIdx.x;
    int wid = t >> 5, wm = wid >> 2, wn = wid & 3;
    int mBase = blockIdx.y * 128, nBase = blockIdx.x * 128;
    int nT = (K + 15) >> 4;

    wmma::fragment<wmma::accumulator, 16, 16, 8, float> acc[4][2];
#pragma unroll
    for (int i = 0; i < 4; i++)
#pragma unroll
        for (int j = 0; j < 2; j++) wmma::fill_fragment(acc[i][j], 0.f);

#define W2_LOAD(k0, buf)                                                     \
    {                                                                        \
        _Pragma("unroll")                                                    \
        for (int p = 0; p < 2; p++) {                                        \
            int id = t + p*256;                                              \
            int m = id >> 2, c4 = id & 3;                                    \
            int gm = mBase + m, gk = (k0) + c4*4;                            \
            int off = (buf)*ASTG + m*SA + c4*4;                              \
            if (gm < M && gk < K) cpa16(smb + off*4, A + (size_t)gm*K + gk); \
            else *(float4*)(sm + off) = make_float4(0.f,0.f,0.f,0.f);        \
        }                                                                    \
        _Pragma("unroll")                                                    \
        for (int p = 0; p < 2; p++) {                                        \
            int id = t + p*256;                                              \
            int kr = id >> 5, n4 = id & 31;                                  \
            int gk = (k0) + kr, gn = nBase + n4*4;                           \
            int off = 2*ASTG + (buf)*BSTG + kr*SB + n4*4;                    \
            if (gk < K && gn < N) cpa16(smb + off*4, B + (size_t)gk*N + gn); \
            else *(float4*)(sm + off) = make_float4(0.f,0.f,0.f,0.f);        \
        }                                                                    \
        cpa_commit();                                                        \
    }

    W2_LOAD(0, 0);
    for (int ti = 0; ti < nT; ti++) {
        int cur = ti & 1;
        if (ti + 1 < nT) { W2_LOAD((ti+1)*16, cur^1); cpa_wait<1>(); }
        else             { cpa_wait<0>(); }
        __syncthreads();
        const float* ap = sm + cur*ASTG;
        const float* bp = sm + 2*ASTG + cur*BSTG;
#pragma unroll
        for (int ks = 0; ks < 2; ks++) {
            int k8 = ks*8;
            wmma::fragment<wmma::matrix_b, 16, 16, 8, wmma::precision::tf32, wmma::row_major> bf[2];
#pragma unroll
            for (int j = 0; j < 2; j++)
                wmma::load_matrix_sync(bf[j], bp + k8*SB + wn*32 + j*16, SB);
#pragma unroll
            for (int i = 0; i < 4; i++) {
                wmma::fragment<wmma::matrix_a, 16, 16, 8, wmma::precision::tf32, wmma::row_major> af;
                wmma::load_matrix_sync(af, ap + (wm*64 + i*16)*SA + k8, SA);
                wmma::mma_sync(acc[i][0], af, bf[0], acc[i][0]);
                wmma::mma_sync(acc[i][1], af, bf[1], acc[i][1]);
            }
        }
        __syncthreads();
    }
#undef W2_LOAD

#pragma unroll
    for (int ph = 0; ph < 2; ph++) {
        if (wm == ph) {
#pragma unroll
            for (int i = 0; i < 4; i++)
#pragma unroll
                for (int j = 0; j < 2; j++)
                    wmma::store_matrix_sync(sm + (i*16)*132 + wn*32 + j*16,
                                            acc[i][j], 132, wmma::mem_row_major);
        }
        __syncthreads();
#pragma unroll
        for (int q = 0; q < 8; q++) {
            int idx = t + q*256;
            int row = idx >> 5, c4 = idx & 31;
            int gm = mBase + ph*64 + row, gn = nBase + c4*4;
            if (gm < M && gn < N) {
                float4 v = *(float4*)&sm[row*132 + c4*4];
                float4 bb = bias ? *(const float4*)&bias[gn] : make_float4(0.f,0.f,0.f,0.f);
                v.x += bb.x; v.y += bb.y; v.z += bb.z; v.w += bb.w;
                if (RELU) {
                    v.x = fmaxf(v.x, 0.f); v.y = fmaxf(v.y, 0.f);
                    v.z = fmaxf(v.z, 0.f); v.w = fmaxf(v.w, 0.f);
                }
                if (C2) {
                    *(float4*)&C[(size_t)gm*N + gn] = v;
                    *(float4*)&C2[(size_t)gm*N + gn] = tf32r4(v);
                } else {
                    if (rnd) v = tf32r4(v);
                    *(float4*)&C[(size_t)gm*N + gn] = v;
                }
            }
        }
        __syncthreads();
    }
}

// ============================================================
// 3) per-sample inverse norm of henc (exact fp32)
// ============================================================
__global__ void k_invnorm(const float* __restrict__ henc, float* __restrict__ invh) {
    int s = blockIdx.x * 8 + (threadIdx.x >> 5);
    int l = threadIdx.x & 31;
    if (s >= NSAMP) return;
    const float4* hp = (const float4*)(henc + (size_t)s*HH);
    float sq = 0.f;
    for (int d4 = l; d4 < 75; d4 += 32) {
        float4 v = hp[d4];
        sq += v.x*v.x + v.y*v.y + v.z*v.z + v.w*v.w;
    }
#pragma unroll
    for (int o = 16; o; o >>= 1) sq += __shfl_down_sync(0xffffffffu, sq, o);
    if (l == 0) invh[s] = 1.0f / (sqrtf(sq) + 1e-8f);
}

// ============================================================
// 4) FUSED cost (WMMA tf32) + masked exp + Sinkhorn (256 thr)
// ============================================================
#define CS_KS   (128*132)
#define CS_AST  (128*20)
#define CS_SMEM ((CS_KS + 4*CS_AST)*4)   // 108544 bytes

__global__ void __launch_bounds__(256, 2)
k_costsink(const float* __restrict__ henct, const float* __restrict__ invh,
           const int* __restrict__ ridx, const int* __restrict__ cidx,
           const int* __restrict__ rlen, const int* __restrict__ clen,
           float* __restrict__ P) {
    int b = blockIdx.x;
    extern __shared__ float sm[];
    float* Ks  = sm;
    float* Ast = sm + CS_KS;
    float* Bst = Ast + 2*CS_AST;
    unsigned int smb = (unsigned int)__cvta_generic_to_shared(sm);
    __shared__ int sr[128], sc[128];
    __shared__ float sir[128], sic[128];
    int t = threadIdx.x;
    int wid = t >> 5, wm = wid >> 2, wn = wid & 3;
    if (t < 128) {
        int i = ridx[b*128 + t];
        sr[t] = i; sir[t] = invh[i];
    } else {
        int i = cidx[b*128 + (t-128)];
        sc[t-128] = i; sic[t-128] = invh[i];
    }
    __syncthreads();

    wmma::fragment<wmma::accumulator, 16, 16, 8, float> acc[4][2];
#pragma unroll
    for (int i = 0; i < 4; i++)
#pragma unroll
        for (int j = 0; j < 2; j++) wmma::fill_fragment(acc[i][j], 0.f);

#define CSW_LOAD(k0, buf)                                                    \
    {                                                                        \
        _Pragma("unroll")                                                    \
        for (int p = 0; p < 2; p++) {                                        \
            int id = t + p*256;                                              \
            int m = id >> 2, c4 = id & 3;                                    \
            int gk = (k0) + c4*4;                                            \
            int offA = CS_KS + (buf)*CS_AST + m*20 + c4*4;                   \
            int offB = CS_KS + 2*CS_AST + (buf)*CS_AST + m*20 + c4*4;        \
            if (gk < 300) {                                                  \
                cpa16(smb + offA*4, henct + (size_t)sr[m]*300 + gk);         \
                cpa16(smb + offB*4, henct + (size_t)sc[m]*300 + gk);         \
            } else {                                                         \
                *(float4*)(sm + offA) = make_float4(0.f,0.f,0.f,0.f);        \
                *(float4*)(sm + offB) = make_float4(0.f,0.f,0.f,0.f);        \
            }                                                                \
        }                                                                    \
        cpa_commit();                                                        \
    }

    CSW_LOAD(0, 0);
    for (int ti = 0; ti < 19; ti++) {
        int cur = ti & 1;
        if (ti + 1 < 19) { CSW_LOAD((ti+1)*16, cur^1); cpa_wait<1>(); }
        else             { cpa_wait<0>(); }
        __syncthreads();
        const float* ap = Ast + cur*CS_AST;
        const float* bp = Bst + cur*CS_AST;
#pragma unroll
        for (int ks = 0; ks < 2; ks++) {
            int k8 = ks*8;
            wmma::fragment<wmma::matrix_b, 16, 16, 8, wmma::precision::tf32, wmma::col_major> bf[2];
#pragma unroll
            for (int j = 0; j < 2; j++)
                wmma::load_matrix_sync(bf[j], bp + (wn*32 + j*16)*20 + k8, 20);
#pragma unroll
            for (int i = 0; i < 4; i++) {
                wmma::fragment<wmma::matrix_a, 16, 16, 8, wmma::precision::tf32, wmma::row_major> af;
                wmma::load_matrix_sync(af, ap + (wm*64 + i*16)*20 + k8, 20);
                wmma::mma_sync(acc[i][0], af, bf[0], acc[i][0]);
                wmma::mma_sync(acc[i][1], af, bf[1], acc[i][1]);
            }
        }
        __syncthreads();
    }
#undef CSW_LOAD

#pragma unroll
    for (int i = 0; i < 4; i++)
#pragma unroll
        for (int j = 0; j < 2; j++)
            wmma::store_matrix_sync(Ks + (wm*64 + i*16)*132 + wn*32 + j*16,
                                    acc[i][j], 132, wmma::mem_row_major);
    __syncthreads();

    int rl = rlen[b], cl = clen[b];
    int r128 = t & 127, half = t >> 7;
    float4 Kreg[16];
    if (r128 < rl) {
        float ir = sir[r128];
#pragma unroll
        for (int m4 = 0; m4 < 16; m4++) {
            int mm = half*64 + m4*4;
            float4 v4 = *(const float4*)&Ks[r128*132 + mm];
            v4.x = (mm+0 < cl) ? __expf((v4.x*ir*sic[mm+0] - 1.0f)*10.0f) : 0.f;
            v4.y = (mm+1 < cl) ? __expf((v4.y*ir*sic[mm+1] - 1.0f)*10.0f) : 0.f;
            v4.z = (mm+2 < cl) ? __expf((v4.z*ir*sic[mm+2] - 1.0f)*10.0f) : 0.f;
            v4.w = (mm+3 < cl) ? __expf((v4.w*ir*sic[mm+3] - 1.0f)*10.0f) : 0.f;
            Kreg[m4] = v4;
            *(float4*)&Ks[r128*132 + mm] = v4;
        }
    } else {
        float4 z4 = make_float4(0.f,0.f,0.f,0.f);
#pragma unroll
        for (int m4 = 0; m4 < 16; m4++) {
            Kreg[m4] = z4;
            *(float4*)&Ks[r128*132 + half*64 + m4*4] = z4;
        }
    }
    __syncthreads();

    float* u   = Ast;
    float* v   = Ast + 128;
    float* red = Ast + 256;
    float ra = 1.0f / (float)rl, rb = 1.0f / (float)cl;
    if (t < 128) u[t] = (t < cl) ? 1.0f : 0.0f;
    __syncthreads();

    int w8 = t >> 5, l32 = t & 31;
    const float4* u4h = (const float4*)(u + half*64);
    for (int it = 0; it < ITERS; it++) {
        float4 s4 = make_float4(0.f,0.f,0.f,0.f);
#pragma unroll
        for (int m = 0; m < 16; m++) {
            float4 uu = u4h[m];
            s4.x += Kreg[m].x*uu.x; s4.y += Kreg[m].y*uu.y;
            s4.z += Kreg[m].z*uu.z; s4.w += Kreg[m].w*uu.w;
        }
        red[half*128 + r128] = (s4.x + s4.y) + (s4.z + s4.w);
        __syncthreads();
        if (t < 128) {
            float s = red[t] + red[128 + t];
            v[t] = (t < rl) ? ra / s : 0.f;
        }
        __syncthreads();
        float4 q4 = make_float4(0.f,0.f,0.f,0.f);
#pragma unroll
        for (int rr = 0; rr < 16; rr++) {
            int n = w8*16 + rr;
            float vn = v[n];
            float4 k4 = *(const float4*)(Ks + n*132 + l32*4);
            q4.x += k4.x*vn; q4.y += k4.y*vn;
            q4.z += k4.z*vn; q4.w += k4.w*vn;
        }
        *(float4*)(red + w8*128 + l32*4) = q4;
        __syncthreads();
        if (t < 128) {
            float q = 0.f;
#pragma unroll
            for (int w = 0; w < 8; w++) q += red[w*128 + t];
            u[t] = (t < cl) ? rb / q : 0.f;
        }
        __syncthreads();
    }
    float ut = u[r128];
    float* Pb = P + (size_t)b*NMX*NMX;
    for (int i = half; i < 128; i += 2)
        Pb[i*128 + r128] = tf32r(v[i] * Ks[i*132 + r128] * ut);
}

// ============================================================
// 5) P-GEMM: 128x160 tiles, 320 thr; single-phase fragment dump +
//    MLP-unrolled epilogue (no live accs during Hc1 loads)
// ============================================================
#define PASTG 2560
#define PC_SMEM (128*SB2*4)   // 83968 B; mainloop stages (10368 fp) overlay

__global__ void __launch_bounds__(320, 2)
k_pcmp_w(const float* __restrict__ P,
         const float* __restrict__ Hc1, const float* __restrict__ Hc2,
         const float* __restrict__ bc,
         const int* __restrict__ ridx, const int* __restrict__ cidx,
         const int* __restrict__ rlen, const int* __restrict__ clen,
         float* __restrict__ cr, float* __restrict__ cc) {
    int b = blockIdx.z, mode = blockIdx.y;
    int hBase = blockIdx.x * 160;
    const int* gidxA = mode ? (ridx + b*128) : (cidx + b*128);
    const int* gidxE = mode ? (cidx + b*128) : (ridx + b*128);
    int len = mode ? clen[b] : rlen[b];
    const float* Pb = P + (size_t)b*NMX*NMX;

    extern __shared__ float sm[];
    unsigned int smb = (unsigned int)__cvta_generic_to_shared(sm);
    __shared__ int sA[128], sE[128];
    __shared__ float red2[320];
    int t = threadIdx.x;
    int wid = t >> 5;
    int wm = wid / 5, wn = wid % 5;
    if (t < 128) sA[t] = gidxA[t];
    else if (t < 256) sE[t-128] = gidxE[t-128];
    __syncthreads();

    wmma::fragment<wmma::accumulator, 16, 16, 8, float> acc[4][2];
#pragma unroll
    for (int i = 0; i < 4; i++)
#pragma unroll
        for (int j = 0; j < 2; j++) wmma::fill_fragment(acc[i][j], 0.f);

#define PCW_LOAD(k0, buf)                                                    \
    {                                                                        \
        if (mode == 0) {                                                     \
            _Pragma("unroll")                                                \
            for (int p = 0; p < 2; p++) {                                    \
                int id = t + p*320;                                          \
                if (id < 512) {                                              \
                    int n = id >> 2, c4 = id & 3;                            \
                    int off = (buf)*PASTG + n*20 + c4*4;                     \
                    cpa16(smb + off*4, Pb + n*128 + (k0) + c4*4);            \
                }                                                            \
            }                                                                \
        } else {                                                             \
            _Pragma("unroll")                                                \
            for (int p = 0; p < 2; p++) {                                    \
                int id = t + p*320;                                          \
                if (id < 512) {                                              \
                    int kr = id >> 5, m4 = id & 31;                          \
                    int off = (buf)*PASTG + kr*132 + m4*4;                   \
                    cpa16(smb + off*4, Pb + ((k0) + kr)*128 + m4*4);         \
                }                                                            \
            }                                                                \
        }                                                                    \
        _Pragma("unroll")                                                    \
        for (int p = 0; p < 2; p++) {                                        \
            int id = t + p*320;                                              \
            int kr = id / 40, n4 = id % 40;                                  \
            int gh = hBase + n4*4;                                           \
            int off = 2*PASTG + (buf)*BSTG2 + kr*SB2 + n4*4;                 \
            if (gh < 300) cpa16(smb + off*4, Hc2 + (size_t)sA[(k0)+kr]*300 + gh);\
            else *(float4*)(sm + off) = make_float4(0.f,0.f,0.f,0.f);        \
        }                                                                    \
        cpa_commit();                                                        \
    }

    PCW_LOAD(0, 0);
    for (int ti = 0; ti < 8; ti++) {
        int cur = ti & 1;
        if (ti + 1 < 8) { PCW_LOAD((ti+1)*16, cur^1); cpa_wait<1>(); }
        else            { cpa_wait<0>(); }
        __syncthreads();
        const float* ap = sm + cur*PASTG;
        const float* bp = sm + 2*PASTG + cur*BSTG2;
#pragma unroll
        for (int ks = 0; ks < 2; ks++) {
            int k8 = ks*8;
            wmma::fragment<wmma::matrix_b, 16, 16, 8, wmma::precision::tf32, wmma::row_major> bf[2];
#pragma unroll
            for (int j = 0; j < 2; j++)
                wmma::load_matrix_sync(bf[j], bp + k8*SB2 + wn*32 + j*16, SB2);
            if (mode == 0) {
#pragma unroll
                for (int i = 0; i < 4; i++) {
                    wmma::fragment<wmma::matrix_a, 16, 16, 8, wmma::precision::tf32, wmma::row_major> af;
                    wmma::load_matrix_sync(af, ap + (wm*64 + i*16)*20 + k8, 20);
                    wmma::mma_sync(acc[i][0], af, bf[0], acc[i][0]);
                    wmma::mma_sync(acc[i][1], af, bf[1], acc[i][1]);
                }
            } else {
#pragma unroll
                for (int i = 0; i < 4; i++) {
                    wmma::fragment<wmma::matrix_a, 16, 16, 8, wmma::precision::tf32, wmma::col_major> af;
                    wmma::load_matrix_sync(af, ap + k8*132 + wm*64 + i*16, 132);
                    wmma::mma_sync(acc[i][0], af, bf[0], acc[i][0]);
                    wmma::mma_sync(acc[i][1], af, bf[1], acc[i][1]);
                }
            }
        }
        __syncthreads();
    }
#undef PCW_LOAD

    // single-phase dump: all 128x160 results land in smem; fragments die
#pragma unroll
    for (int i = 0; i < 4; i++)
#pragma unroll
        for (int j = 0; j < 2; j++)
            wmma::store_matrix_sync(sm + (wm*64 + i*16)*SB2 + wn*32 + j*16,
                                    acc[i][j], SB2, wmma::mem_row_major);
    __syncthreads();

    // MLP-unrolled reduction: thread = (h col, 64-row half)
    int hc = t % 160, rh = t / 160;
    int hg = hBase + hc;
    float outv = 0.f;
    if (hg < 300) {
        float bcv = bc[hg];
        int rbase = rh * 64;
        float s0 = 0.f, s1 = 0.f, s2 = 0.f, s3 = 0.f;
#pragma unroll 4
        for (int r = 0; r < 64; r += 4) {
            int g0 = rbase + r;
            float a0 = (g0+0 < len) ? fmaxf(sm[(g0+0)*SB2 + hc] + Hc1[(size_t)sE[g0+0]*300 + hg] + bcv, 0.f) : 0.f;
            float a1 = (g0+1 < len) ? fmaxf(sm[(g0+1)*SB2 + hc] + Hc1[(size_t)sE[g0+1]*300 + hg] + bcv, 0.f) : 0.f;
            float a2 = (g0+2 < len) ? fmaxf(sm[(g0+2)*SB2 + hc] + Hc1[(size_t)sE[g0+2]*300 + hg] + bcv, 0.f) : 0.f;
            float a3 = (g0+3 < len) ? fmaxf(sm[(g0+3)*SB2 + hc] + Hc1[(size_t)sE[g0+3]*300 + hg] + bcv, 0.f) : 0.f;
            s0 += a0; s1 += a1; s2 += a2; s3 += a3;
        }
        outv = (s0 + s1) + (s2 + s3);
    }
    red2[t] = outv;
    __syncthreads();
    if (t < 160 && hg < 300) {
        float* outp = mode ? cc : cr;
        outp[b*HH + hg] = red2[t] + red2[t + 160];
    }
}

// ============================================================
// 6) classifier head
// ============================================================
__global__ void k_cls(const float* __restrict__ cr,
                      const float* __restrict__ cc,
                      const float* __restrict__ Wcls,
                      const float* __restrict__ bcls,
                      const float* __restrict__ Wout,
                      const float* __restrict__ bout,
                      float* __restrict__ out) {
    int b = blockIdx.x;
    int t = threadIdx.x;              // 320 threads
    __shared__ float x[2*HH];
    for (int i = t; i < 2*HH; i += 320)
        x[i] = (i < HH) ? cr[b*HH + i] : cc[b*HH + i - HH];
    __syncthreads();
    float z = 0.f;
    if (t < HH) {
        float a0 = 0.f, a1 = 0.f, a2 = 0.f, a3 = 0.f;
#pragma unroll 4
        for (int k = 0; k < 2*HH; k += 4) {
            a0 += x[k+0]*Wcls[(k+0)*HH + t];
            a1 += x[k+1]*Wcls[(k+1)*HH + t];
            a2 += x[k+2]*Wcls[(k+2)*HH + t];
            a3 += x[k+3]*Wcls[(k+3)*HH + t];
        }
        z = fmaxf((a0+a1)+(a2+a3) + bcls[t], 0.f);
    }
    float s0 = (t < HH) ? z*Wout[t*2 + 0] : 0.f;
    float s1 = (t < HH) ? z*Wout[t*2 + 1] : 0.f;
#pragma unroll
    for (int o = 16; o; o >>= 1) {
        s0 += __shfl_down_sync(0xffffffffu, s0, o);
        s1 += __shfl_down_sync(0xffffffffu, s1, o);
    }
    __shared__ float r0[10], r1[10];
    if ((t & 31) == 0) { r0[t >> 5] = s0; r1[t >> 5] = s1; }
    __syncthreads();
    if (t == 0) {
        float a = 0.f, c = 0.f;
#pragma unroll
        for (int i = 0; i < 10; i++) { a += r0[i]; c += r1[i]; }
        out[b*2 + 0] = a + bout[0];
        out[b*2 + 1] = c + bout[1];
    }
}

// ============================================================
// launch
// ============================================================
extern "C" void kernel_launch(void* const* d_in, const int* in_sizes, int n_in,
                              void* d_out, int out_size) {
    const int*   data    = (const int*)  d_in[0];
    const int*   row_idx = (const int*)  d_in[1];
    const int*   col_idx = (const int*)  d_in[2];
    const int*   row_len = (const int*)  d_in[3];
    const int*   col_len = (const int*)  d_in[4];
    const float* emb     = (const float*)d_in[5];
    const float* W1      = (const float*)d_in[6];
    const float* b1      = (const float*)d_in[7];
    const float* W2      = (const float*)d_in[8];
    const float* b2      = (const float*)d_in[9];
    const float* Wc      = (const float*)d_in[10];
    const float* bc      = (const float*)d_in[11];
    const float* Wcls    = (const float*)d_in[12];
    const float* bcls    = (const float*)d_in[13];
    const float* Wout    = (const float*)d_in[14];
    const float* bout    = (const float*)d_in[15];
    float* out = (float*)d_out;

    float *enc, *h1, *henc, *henct, *Hc, *Wr, *invh, *Pb, *cr, *cc;
    cudaGetSymbolAddress((void**)&enc,   g_enc);
    cudaGetSymbolAddress((void**)&h1,    g_h1);
    cudaGetSymbolAddress((void**)&henc,  g_henc);
    cudaGetSymbolAddress((void**)&henct, g_henct);
    cudaGetSymbolAddress((void**)&Hc,    g_Hc);
    cudaGetSymbolAddress((void**)&Wr,    g_Wr);
    cudaGetSymbolAddress((void**)&invh,  g_invh);
    cudaGetSymbolAddress((void**)&Pb,    g_Pmat);
    cudaGetSymbolAddress((void**)&cr,    g_cr);
    cudaGetSymbolAddress((void**)&cc,    g_cc);
    float* W1r = Wr;
    float* W2r = Wr + HH*HH;
    float* Wcr = Wr + 2*HH*HH;
    float* Hc1 = Hc;
    float* Hc2 = Hc + (long)NSAMP*HH;

    cudaFuncSetAttribute(k_wgemm2<true>,  cudaFuncAttributeMaxDynamicSharedMemorySize, WG2_SMEM);
    cudaFuncSetAttribute(k_wgemm2<false>, cudaFuncAttributeMaxDynamicSharedMemorySize, WG2_SMEM);
    cudaFuncSetAttribute(k_costsink, cudaFuncAttributeMaxDynamicSharedMemorySize, CS_SMEM);
    cudaFuncSetAttribute(k_pcmp_w, cudaFuncAttributeMaxDynamicSharedMemorySize, PC_SMEM);

    // 0) round weights into scratch
    k_roundw<<<(2*HH*HH + 255)/256, 256>>>(W1, W2, Wc, Wr);
    // 1) embedding pool (enc rounded to tf32)
    k_embed<<<NSAMP, 320>>>(data, emb, enc);
    // 2) FFN (128-wide N tiles — grid 237)
    dim3 gF(3, 79, 1);
    k_wgemm2<true><<<gF, 256, WG2_SMEM>>>(enc, W1r, b1, h1, nullptr,
                                          NSAMP, HH, DD, 0, 0, 1);
    k_wgemm2<true><<<gF, 256, WG2_SMEM>>>(h1, W2r, b2, henc, henct,
                                          NSAMP, HH, HH, 0, 0, 0);

    // fork: Hc GEMM on side stream
    cudaEventRecord(g_hx.eHenc, 0);
    cudaStreamWaitEvent(g_hx.sB, g_hx.eHenc, 0);
    dim3 gHc(3, 79, 2);
    k_wgemm2<false><<<gHc, 256, WG2_SMEM, g_hx.sB>>>(henct, Wcr, nullptr, Hc, nullptr,
                                                     NSAMP, HH, HH, (long)HH*HH,
                                                     (long)NSAMP*HH, 2);
    cudaEventRecord(g_hx.eHc, g_hx.sB);

    // chain A: fused WMMA cost + masked exp + Sinkhorn
    k_invnorm<<<(NSAMP + 7)/8, 256>>>(henc, invh);
    k_costsink<<<BB, 256, CS_SMEM>>>(henct, invh, row_idx, col_idx,
                                     row_len, col_len, Pb);

    // join: pcmp with 160-wide tiles + MLP epilogue
    cudaStreamWaitEvent(0, g_hx.eHc, 0);
    k_pcmp_w<<<dim3(2, 2, BB), 320, PC_SMEM>>>(Pb, Hc1, Hc2, bc, row_idx, col_idx,
                                               row_len, col_len, cr, cc);
    k_cls<<<BB, 320>>>(cr, cc, Wcls, bcls, Wout, bout, out);
}

// round 15
// speedup vs baseline: 1.0010x; 1.0010x over previous
#include <cuda_runtime.h>
#include <math.h>
#include <mma.h>
using namespace nvcuda;

// ---- problem dims ----
#define NSAMP 10000
#define LTOK  32
#define DD    300
#define HH    300
#define BB    256
#define NMX   128
#define ITERS 50

// ---- scratch ----
__device__ float g_enc [NSAMP*DD];
__device__ float g_h1  [NSAMP*HH];
__device__ float g_henc[NSAMP*HH];
__device__ float g_henct[NSAMP*HH];
__device__ float g_Hc  [2*NSAMP*HH];
__device__ float g_Wr  [4*HH*HH];
__device__ float g_invh[NSAMP];
__device__ float g_Pmat[BB*NMX*NMX];
__device__ float g_cr  [BB*HH];
__device__ float g_cc  [BB*HH];

// ---- streams/events (static init, pre-checkpoint) ----
struct HxStreams {
    cudaStream_t sB;
    cudaEvent_t eHenc, eHc;
    HxStreams() {
        cudaStreamCreateWithFlags(&sB, cudaStreamNonBlocking);
        cudaEventCreateWithFlags(&eHenc, cudaEventDisableTiming);
        cudaEventCreateWithFlags(&eHc,   cudaEventDisableTiming);
    }
};
static HxStreams g_hx;

// ---- cp.async helpers ----
__device__ __forceinline__ void cpa16(unsigned int dst, const void* src) {
    asm volatile("cp.async.ca.shared.global [%0], [%1], 16;" :: "r"(dst), "l"(src));
}
__device__ __forceinline__ void cpa_commit() {
    asm volatile("cp.async.commit_group;");
}
template<int NN> __device__ __forceinline__ void cpa_wait() {
    asm volatile("cp.async.wait_group %0;" :: "n"(NN));
}

__device__ __forceinline__ float tf32r(float x) { return wmma::__float_to_tf32(x); }
__device__ __forceinline__ float4 tf32r4(float4 v) {
    v.x = tf32r(v.x); v.y = tf32r(v.y); v.z = tf32r(v.z); v.w = tf32r(v.w);
    return v;
}

// ============================================================
// 0) pre-round weights to tf32 (RN) into scratch
// ============================================================
__global__ void k_roundw(const float* __restrict__ W1, const float* __restrict__ W2,
                         const float* __restrict__ Wc, float* __restrict__ Wr) {
    int i = blockIdx.x * 256 + threadIdx.x;
    if (i < HH*HH)   Wr[i]           = tf32r(W1[i]);
    if (i < HH*HH)   Wr[HH*HH + i]   = tf32r(W2[i]);
    if (i < 2*HH*HH) Wr[2*HH*HH + i] = tf32r(Wc[i]);
}

// ============================================================
// 1) embedding + masked mean pool (output rounded to tf32)
// ============================================================
__global__ void k_embed(const int* __restrict__ data,
                        const float* __restrict__ emb,
                        float* __restrict__ enc) {
    int s = blockIdx.x;
    int t = threadIdx.x;            // 320 threads
    __shared__ int toks[LTOK];
    if (t < LTOK) toks[t] = data[s*LTOK + t];
    __syncthreads();
    int cnt = 0;
#pragma unroll
    for (int l = 0; l < LTOK; l++) cnt += (toks[l] != 0);
    float inv = 1.0f / (float)(cnt > 0 ? cnt : 1);
    if (t < DD) {
        float acc = 0.f;
#pragma unroll
        for (int l = 0; l < LTOK; l++) {
            int tok = toks[l];
            if (tok != 0) acc += emb[tok*DD + t];
        }
        enc[s*DD + t] = tf32r(acc * inv);
    }
}

// ============================================================
// 2) WMMA tf32 GEMM: 128x128 tile, BK=32 (half the barriers),
//    cp.async double buffer, 256 thr / 8 warps (2m x 4n)
// ============================================================
#define SA32  36
#define SB    132
#define SB2   164
#define AST32 (128*SA32)      // 4608 floats
#define BST32 (32*SB)         // 4224 floats
#define BSTG2 (16*SB2)
#define WG2_SMEM (2*(AST32+BST32)*4)   // 70656 bytes

template<bool RELU>
__global__ void __launch_bounds__(256, 2)
k_wgemm2(const float* __restrict__ A, const float* __restrict__ B,
         const float* __restrict__ bias, float* __restrict__ C, float* __restrict__ C2,
         int M, int N, int K, long bStride, long cStride, int round_mask) {
    B += (long)blockIdx.z * bStride;
    C += (long)blockIdx.z * cStride;
    bool rnd = (round_mask >> blockIdx.z) & 1;
    extern __shared__ float sm[];
    unsigned int smb = (unsigned int)__cvta_generic_to_shared(sm);
    int t = threadIdx.x;
    int wid = t >> 5, wm = wid >> 2, wn = wid & 3;
    int mBase = blockIdx.y * 128, nBase = blockIdx.x * 128;
    int nT = (K + 31) >> 5;

    wmma::fragment<wmma::accumulator, 16, 16, 8, float> acc[4][2];
#pragma unroll
    for (int i = 0; i < 4; i++)
#pragma unroll
        for (int j = 0; j < 2; j++) wmma::fill_fragment(acc[i][j], 0.f);

#define W2_LOAD(k0, buf)                                                     \
    {                                                                        \
        _Pragma("unroll")                                                    \
        for (int p = 0; p < 4; p++) {                                        \
            int id = t + p*256;                                              \
            int m = id >> 3, c4 = id & 7;                                    \
            int gm = mBase + m, gk = (k0) + c4*4;                            \
            int off = (buf)*AST32 + m*SA32 + c4*4;                           \
            if (gm < M && gk < K) cpa16(smb + off*4, A + (size_t)gm*K + gk); \
            else *(float4*)(sm + off) = make_float4(0.f,0.f,0.f,0.f);        \
        }                                                                    \
        _Pragma("unroll")                                                    \
        for (int p = 0; p < 4; p++) {                                        \
            int id = t + p*256;                                              \
            int kr = id >> 5, n4 = id & 31;                                  \
            int gk = (k0) + kr, gn = nBase + n4*4;                           \
            int off = 2*AST32 + (buf)*BST32 + kr*SB + n4*4;                  \
            if (gk < K && gn < N) cpa16(smb + off*4, B + (size_t)gk*N + gn); \
            else *(float4*)(sm + off) = make_float4(0.f,0.f,0.f,0.f);        \
        }                                                                    \
        cpa_commit();                                                        \
    }

    W2_LOAD(0, 0);
    for (int ti = 0; ti < nT; ti++) {
        int cur = ti & 1;
        if (ti + 1 < nT) { W2_LOAD((ti+1)*32, cur^1); cpa_wait<1>(); }
        else             { cpa_wait<0>(); }
        __syncthreads();
        const float* ap = sm + cur*AST32;
        const float* bp = sm + 2*AST32 + cur*BST32;
#pragma unroll
        for (int ks = 0; ks < 4; ks++) {
            int k8 = ks*8;
            wmma::fragment<wmma::matrix_b, 16, 16, 8, wmma::precision::tf32, wmma::row_major> bf[2];
#pragma unroll
            for (int j = 0; j < 2; j++)
                wmma::load_matrix_sync(bf[j], bp + k8*SB + wn*32 + j*16, SB);
#pragma unroll
            for (int i = 0; i < 4; i++) {
                wmma::fragment<wmma::matrix_a, 16, 16, 8, wmma::precision::tf32, wmma::row_major> af;
                wmma::load_matrix_sync(af, ap + (wm*64 + i*16)*SA32 + k8, SA32);
                wmma::mma_sync(acc[i][0], af, bf[0], acc[i][0]);
                wmma::mma_sync(acc[i][1], af, bf[1], acc[i][1]);
            }
        }
        __syncthreads();
    }
#undef W2_LOAD

#pragma unroll
    for (int ph = 0; ph < 2; ph++) {
        if (wm == ph) {
#pragma unroll
            for (int i = 0; i < 4; i++)
#pragma unroll
                for (int j = 0; j < 2; j++)
                    wmma::store_matrix_sync(sm + (i*16)*132 + wn*32 + j*16,
                                            acc[i][j], 132, wmma::mem_row_major);
        }
        __syncthreads();
#pragma unroll
        for (int q = 0; q < 8; q++) {
            int idx = t + q*256;
            int row = idx >> 5, c4 = idx & 31;
            int gm = mBase + ph*64 + row, gn = nBase + c4*4;
            if (gm < M && gn < N) {
                float4 v = *(float4*)&sm[row*132 + c4*4];
                float4 bb = bias ? *(const float4*)&bias[gn] : make_float4(0.f,0.f,0.f,0.f);
                v.x += bb.x; v.y += bb.y; v.z += bb.z; v.w += bb.w;
                if (RELU) {
                    v.x = fmaxf(v.x, 0.f); v.y = fmaxf(v.y, 0.f);
                    v.z = fmaxf(v.z, 0.f); v.w = fmaxf(v.w, 0.f);
                }
                if (C2) {
                    *(float4*)&C[(size_t)gm*N + gn] = v;
                    *(float4*)&C2[(size_t)gm*N + gn] = tf32r4(v);
                } else {
                    if (rnd) v = tf32r4(v);
                    *(float4*)&C[(size_t)gm*N + gn] = v;
                }
            }
        }
        __syncthreads();
    }
}

// ============================================================
// 3) per-sample inverse norm of henc (exact fp32)
// ============================================================
__global__ void k_invnorm(const float* __restrict__ henc, float* __restrict__ invh) {
    int s = blockIdx.x * 8 + (threadIdx.x >> 5);
    int l = threadIdx.x & 31;
    if (s >= NSAMP) return;
    const float4* hp = (const float4*)(henc + (size_t)s*HH);
    float sq = 0.f;
    for (int d4 = l; d4 < 75; d4 += 32) {
        float4 v = hp[d4];
        sq += v.x*v.x + v.y*v.y + v.z*v.z + v.w*v.w;
    }
#pragma unroll
    for (int o = 16; o; o >>= 1) sq += __shfl_down_sync(0xffffffffu, sq, o);
    if (l == 0) invh[s] = 1.0f / (sqrtf(sq) + 1e-8f);
}

// ============================================================
// 4) FUSED cost (WMMA tf32) + masked exp + Sinkhorn (unchanged)
// ============================================================
#define CS_KS   (128*132)
#define CS_AST  (128*20)
#define CS_SMEM ((CS_KS + 4*CS_AST)*4)   // 108544 bytes

__global__ void __launch_bounds__(256, 2)
k_costsink(const float* __restrict__ henct, const float* __restrict__ invh,
           const int* __restrict__ ridx, const int* __restrict__ cidx,
           const int* __restrict__ rlen, const int* __restrict__ clen,
           float* __restrict__ P) {
    int b = blockIdx.x;
    extern __shared__ float sm[];
    float* Ks  = sm;
    float* Ast = sm + CS_KS;
    float* Bst = Ast + 2*CS_AST;
    unsigned int smb = (unsigned int)__cvta_generic_to_shared(sm);
    __shared__ int sr[128], sc[128];
    __shared__ float sir[128], sic[128];
    int t = threadIdx.x;
    int wid = t >> 5, wm = wid >> 2, wn = wid & 3;
    if (t < 128) {
        int i = ridx[b*128 + t];
        sr[t] = i; sir[t] = invh[i];
    } else {
        int i = cidx[b*128 + (t-128)];
        sc[t-128] = i; sic[t-128] = invh[i];
    }
    __syncthreads();

    wmma::fragment<wmma::accumulator, 16, 16, 8, float> acc[4][2];
#pragma unroll
    for (int i = 0; i < 4; i++)
#pragma unroll
        for (int j = 0; j < 2; j++) wmma::fill_fragment(acc[i][j], 0.f);

#define CSW_LOAD(k0, buf)                                                    \
    {                                                                        \
        _Pragma("unroll")                                                    \
        for (int p = 0; p < 2; p++) {                                        \
            int id = t + p*256;                                              \
            int m = id >> 2, c4 = id & 3;                                    \
            int gk = (k0) + c4*4;                                            \
            int offA = CS_KS + (buf)*CS_AST + m*20 + c4*4;                   \
            int offB = CS_KS + 2*CS_AST + (buf)*CS_AST + m*20 + c4*4;        \
            if (gk < 300) {                                                  \
                cpa16(smb + offA*4, henct + (size_t)sr[m]*300 + gk);         \
                cpa16(smb + offB*4, henct + (size_t)sc[m]*300 + gk);         \
            } else {                                                         \
                *(float4*)(sm + offA) = make_float4(0.f,0.f,0.f,0.f);        \
                *(float4*)(sm + offB) = make_float4(0.f,0.f,0.f,0.f);        \
            }                                                                \
        }                                                                    \
        cpa_commit();                                                        \
    }

    CSW_LOAD(0, 0);
    for (int ti = 0; ti < 19; ti++) {
        int cur = ti & 1;
        if (ti + 1 < 19) { CSW_LOAD((ti+1)*16, cur^1); cpa_wait<1>(); }
        else             { cpa_wait<0>(); }
        __syncthreads();
        const float* ap = Ast + cur*CS_AST;
        const float* bp = Bst + cur*CS_AST;
#pragma unroll
        for (int ks = 0; ks < 2; ks++) {
            int k8 = ks*8;
            wmma::fragment<wmma::matrix_b, 16, 16, 8, wmma::precision::tf32, wmma::col_major> bf[2];
#pragma unroll
            for (int j = 0; j < 2; j++)
                wmma::load_matrix_sync(bf[j], bp + (wn*32 + j*16)*20 + k8, 20);
#pragma unroll
            for (int i = 0; i < 4; i++) {
                wmma::fragment<wmma::matrix_a, 16, 16, 8, wmma::precision::tf32, wmma::row_major> af;
                wmma::load_matrix_sync(af, ap + (wm*64 + i*16)*20 + k8, 20);
                wmma::mma_sync(acc[i][0], af, bf[0], acc[i][0]);
                wmma::mma_sync(acc[i][1], af, bf[1], acc[i][1]);
            }
        }
        __syncthreads();
    }
#undef CSW_LOAD

#pragma unroll
    for (int i = 0; i < 4; i++)
#pragma unroll
        for (int j = 0; j < 2; j++)
            wmma::store_matrix_sync(Ks + (wm*64 + i*16)*132 + wn*32 + j*16,
                                    acc[i][j], 132, wmma::mem_row_major);
    __syncthreads();

    int rl = rlen[b], cl = clen[b];
    int r128 = t & 127, half = t >> 7;
    float4 Kreg[16];
    if (r128 < rl) {
        float ir = sir[r128];
#pragma unroll
        for (int m4 = 0; m4 < 16; m4++) {
            int mm = half*64 + m4*4;
            float4 v4 = *(const float4*)&Ks[r128*132 + mm];
            v4.x = (mm+0 < cl) ? __expf((v4.x*ir*sic[mm+0] - 1.0f)*10.0f) : 0.f;
            v4.y = (mm+1 < cl) ? __expf((v4.y*ir*sic[mm+1] - 1.0f)*10.0f) : 0.f;
            v4.z = (mm+2 < cl) ? __expf((v4.z*ir*sic[mm+2] - 1.0f)*10.0f) : 0.f;
            v4.w = (mm+3 < cl) ? __expf((v4.w*ir*sic[mm+3] - 1.0f)*10.0f) : 0.f;
            Kreg[m4] = v4;
            *(float4*)&Ks[r128*132 + mm] = v4;
        }
    } else {
        float4 z4 = make_float4(0.f,0.f,0.f,0.f);
#pragma unroll
        for (int m4 = 0; m4 < 16; m4++) {
            Kreg[m4] = z4;
            *(float4*)&Ks[r128*132 + half*64 + m4*4] = z4;
        }
    }
    __syncthreads();

    float* u   = Ast;
    float* v   = Ast + 128;
    float* red = Ast + 256;
    float ra = 1.0f / (float)rl, rb = 1.0f / (float)cl;
    if (t < 128) u[t] = (t < cl) ? 1.0f : 0.0f;
    __syncthreads();

    int w8 = t >> 5, l32 = t & 31;
    const float4* u4h = (const float4*)(u + half*64);
    for (int it = 0; it < ITERS; it++) {
        float4 s4 = make_float4(0.f,0.f,0.f,0.f);
#pragma unroll
        for (int m = 0; m < 16; m++) {
            float4 uu = u4h[m];
            s4.x += Kreg[m].x*uu.x; s4.y += Kreg[m].y*uu.y;
            s4.z += Kreg[m].z*uu.z; s4.w += Kreg[m].w*uu.w;
        }
        red[half*128 + r128] = (s4.x + s4.y) + (s4.z + s4.w);
        __syncthreads();
        if (t < 128) {
            float s = red[t] + red[128 + t];
            v[t] = (t < rl) ? ra / s : 0.f;
        }
        __syncthreads();
        float4 q4 = make_float4(0.f,0.f,0.f,0.f);
#pragma unroll
        for (int rr = 0; rr < 16; rr++) {
            int n = w8*16 + rr;
            float vn = v[n];
            float4 k4 = *(const float4*)(Ks + n*132 + l32*4);
            q4.x += k4.x*vn; q4.y += k4.y*vn;
            q4.z += k4.z*vn; q4.w += k4.w*vn;
        }
        *(float4*)(red + w8*128 + l32*4) = q4;
        __syncthreads();
        if (t < 128) {
            float q = 0.f;
#pragma unroll
            for (int w = 0; w < 8; w++) q += red[w*128 + t];
            u[t] = (t < cl) ? rb / q : 0.f;
        }
        __syncthreads();
    }
    float ut = u[r128];
    float* Pb = P + (size_t)b*NMX*NMX;
    for (int i = half; i < 128; i += 2)
        Pb[i*128 + r128] = tf32r(v[i] * Ks[i*132 + r128] * ut);
}

// ============================================================
// 5) P-GEMM (R13 best config): 128x160 tiles, 320 thr,
//    two-phase fragment dump + fused compare epilogue
// ============================================================
#define PASTG 2560
#define PC_SMEM (64*SB2*4)   // 41984 B

__global__ void __launch_bounds__(320, 2)
k_pcmp_w(const float* __restrict__ P,
         const float* __restrict__ Hc1, const float* __restrict__ Hc2,
         const float* __restrict__ bc,
         const int* __restrict__ ridx, const int* __restrict__ cidx,
         const int* __restrict__ rlen, const int* __restrict__ clen,
         float* __restrict__ cr, float* __restrict__ cc) {
    int b = blockIdx.z, mode = blockIdx.y;
    int hBase = blockIdx.x * 160;
    const int* gidxA = mode ? (ridx + b*128) : (cidx + b*128);
    const int* gidxE = mode ? (cidx + b*128) : (ridx + b*128);
    int len = mode ? clen[b] : rlen[b];
    const float* Pb = P + (size_t)b*NMX*NMX;

    extern __shared__ float sm[];
    unsigned int smb = (unsigned int)__cvta_generic_to_shared(sm);
    __shared__ int sA[128], sE[128];
    __shared__ float red2[320];
    int t = threadIdx.x;
    int wid = t >> 5;
    int wm = wid / 5, wn = wid % 5;
    if (t < 128) sA[t] = gidxA[t];
    else if (t < 256) sE[t-128] = gidxE[t-128];
    __syncthreads();

    wmma::fragment<wmma::accumulator, 16, 16, 8, float> acc[4][2];
#pragma unroll
    for (int i = 0; i < 4; i++)
#pragma unroll
        for (int j = 0; j < 2; j++) wmma::fill_fragment(acc[i][j], 0.f);

#define PCW_LOAD(k0, buf)                                                    \
    {                                                                        \
        if (mode == 0) {                                                     \
            _Pragma("unroll")                                                \
            for (int p = 0; p < 2; p++) {                                    \
                int id = t + p*320;                                          \
                if (id < 512) {                                              \
                    int n = id >> 2, c4 = id & 3;                            \
                    int off = (buf)*PASTG + n*20 + c4*4;                     \
                    cpa16(smb + off*4, Pb + n*128 + (k0) + c4*4);            \
                }                                                            \
            }                                                                \
        } else {                                                             \
            _Pragma("unroll")                                                \
            for (int p = 0; p < 2; p++) {                                    \
                int id = t + p*320;                                          \
                if (id < 512) {                                              \
                    int kr = id >> 5, m4 = id & 31;                          \
                    int off = (buf)*PASTG + kr*132 + m4*4;                   \
                    cpa16(smb + off*4, Pb + ((k0) + kr)*128 + m4*4);         \
                }                                                            \
            }                                                                \
        }                                                                    \
        _Pragma("unroll")                                                    \
        for (int p = 0; p < 2; p++) {                                        \
            int id = t + p*320;                                              \
            int kr = id / 40, n4 = id % 40;                                  \
            int gh = hBase + n4*4;                                           \
            int off = 2*PASTG + (buf)*BSTG2 + kr*SB2 + n4*4;                 \
            if (gh < 300) cpa16(smb + off*4, Hc2 + (size_t)sA[(k0)+kr]*300 + gh);\
            else *(float4*)(sm + off) = make_float4(0.f,0.f,0.f,0.f);        \
        }                                                                    \
        cpa_commit();                                                        \
    }

    PCW_LOAD(0, 0);
    for (int ti = 0; ti < 8; ti++) {
        int cur = ti & 1;
        if (ti + 1 < 8) { PCW_LOAD((ti+1)*16, cur^1); cpa_wait<1>(); }
        else            { cpa_wait<0>(); }
        __syncthreads();
        const float* ap = sm + cur*PASTG;
        const float* bp = sm + 2*PASTG + cur*BSTG2;
#pragma unroll
        for (int ks = 0; ks < 2; ks++) {
            int k8 = ks*8;
            wmma::fragment<wmma::matrix_b, 16, 16, 8, wmma::precision::tf32, wmma::row_major> bf[2];
#pragma unroll
            for (int j = 0; j < 2; j++)
                wmma::load_matrix_sync(bf[j], bp + k8*SB2 + wn*32 + j*16, SB2);
            if (mode == 0) {
#pragma unroll
                for (int i = 0; i < 4; i++) {
                    wmma::fragment<wmma::matrix_a, 16, 16, 8, wmma::precision::tf32, wmma::row_major> af;
                    wmma::load_matrix_sync(af, ap + (wm*64 + i*16)*20 + k8, 20);
                    wmma::mma_sync(acc[i][0], af, bf[0], acc[i][0]);
                    wmma::mma_sync(acc[i][1], af, bf[1], acc[i][1]);
                }
            } else {
#pragma unroll
                for (int i = 0; i < 4; i++) {
                    wmma::fragment<wmma::matrix_a, 16, 16, 8, wmma::precision::tf32, wmma::col_major> af;
                    wmma::load_matrix_sync(af, ap + k8*132 + wm*64 + i*16, 132);
                    wmma::mma_sync(acc[i][0], af, bf[0], acc[i][0]);
                    wmma::mma_sync(acc[i][1], af, bf[1], acc[i][1]);
                }
            }
        }
        __syncthreads();
    }
#undef PCW_LOAD

    float colsum = 0.f;
    int hc = t % 160, rh = t / 160;
    int hg = hBase + hc;
    float bcv = (hg < 300) ? bc[hg] : 0.f;
#pragma unroll
    for (int ph = 0; ph < 2; ph++) {
        if (wm == ph) {
#pragma unroll
            for (int i = 0; i < 4; i++)
#pragma unroll
                for (int j = 0; j < 2; j++)
                    wmma::store_matrix_sync(sm + (i*16)*SB2 + wn*32 + j*16,
                                            acc[i][j], SB2, wmma::mem_row_major);
        }
        __syncthreads();
        if (hg < 300) {
            for (int r = rh*32; r < rh*32 + 32; r++) {
                int gr = ph*64 + r;
                if (gr < len)
                    colsum += fmaxf(sm[r*SB2 + hc] + Hc1[(size_t)sE[gr]*300 + hg] + bcv, 0.f);
            }
        }
        __syncthreads();
    }
    red2[t] = colsum;
    __syncthreads();
    if (t < 160 && hg < 300) {
        float* outp = mode ? cc : cr;
        outp[b*HH + hg] = red2[t] + red2[t + 160];
    }
}

// ============================================================
// 6) classifier head
// ============================================================
__global__ void k_cls(const float* __restrict__ cr,
                      const float* __restrict__ cc,
                      const float* __restrict__ Wcls,
                      const float* __restrict__ bcls,
                      const float* __restrict__ Wout,
                      const float* __restrict__ bout,
                      float* __restrict__ out) {
    int b = blockIdx.x;
    int t = threadIdx.x;              // 320 threads
    __shared__ float x[2*HH];
    for (int i = t; i < 2*HH; i += 320)
        x[i] = (i < HH) ? cr[b*HH + i] : cc[b*HH + i - HH];
    __syncthreads();
    float z = 0.f;
    if (t < HH) {
        float a0 = 0.f, a1 = 0.f, a2 = 0.f, a3 = 0.f;
#pragma unroll 4
        for (int k = 0; k < 2*HH; k += 4) {
            a0 += x[k+0]*Wcls[(k+0)*HH + t];
            a1 += x[k+1]*Wcls[(k+1)*HH + t];
            a2 += x[k+2]*Wcls[(k+2)*HH + t];
            a3 += x[k+3]*Wcls[(k+3)*HH + t];
        }
        z = fmaxf((a0+a1)+(a2+a3) + bcls[t], 0.f);
    }
    float s0 = (t < HH) ? z*Wout[t*2 + 0] : 0.f;
    float s1 = (t < HH) ? z*Wout[t*2 + 1] : 0.f;
#pragma unroll
    for (int o = 16; o; o >>= 1) {
        s0 += __shfl_down_sync(0xffffffffu, s0, o);
        s1 += __shfl_down_sync(0xffffffffu, s1, o);
    }
    __shared__ float r0[10], r1[10];
    if ((t & 31) == 0) { r0[t >> 5] = s0; r1[t >> 5] = s1; }
    __syncthreads();
    if (t == 0) {
        float a = 0.f, c = 0.f;
#pragma unroll
        for (int i = 0; i < 10; i++) { a += r0[i]; c += r1[i]; }
        out[b*2 + 0] = a + bout[0];
        out[b*2 + 1] = c + bout[1];
    }
}

// ============================================================
// launch
// ============================================================
extern "C" void kernel_launch(void* const* d_in, const int* in_sizes, int n_in,
                              void* d_out, int out_size) {
    const int*   data    = (const int*)  d_in[0];
    const int*   row_idx = (const int*)  d_in[1];
    const int*   col_idx = (const int*)  d_in[2];
    const int*   row_len = (const int*)  d_in[3];
    const int*   col_len = (const int*)  d_in[4];
    const float* emb     = (const float*)d_in[5];
    const float* W1      = (const float*)d_in[6];
    const float* b1      = (const float*)d_in[7];
    const float* W2      = (const float*)d_in[8];
    const float* b2      = (const float*)d_in[9];
    const float* Wc      = (const float*)d_in[10];
    const float* bc      = (const float*)d_in[11];
    const float* Wcls    = (const float*)d_in[12];
    const float* bcls    = (const float*)d_in[13];
    const float* Wout    = (const float*)d_in[14];
    const float* bout    = (const float*)d_in[15];
    float* out = (float*)d_out;

    float *enc, *h1, *henc, *henct, *Hc, *Wr, *invh, *Pb, *cr, *cc;
    cudaGetSymbolAddress((void**)&enc,   g_enc);
    cudaGetSymbolAddress((void**)&h1,    g_h1);
    cudaGetSymbolAddress((void**)&henc,  g_henc);
    cudaGetSymbolAddress((void**)&henct, g_henct);
    cudaGetSymbolAddress((void**)&Hc,    g_Hc);
    cudaGetSymbolAddress((void**)&Wr,    g_Wr);
    cudaGetSymbolAddress((void**)&invh,  g_invh);
    cudaGetSymbolAddress((void**)&Pb,    g_Pmat);
    cudaGetSymbolAddress((void**)&cr,    g_cr);
    cudaGetSymbolAddress((void**)&cc,    g_cc);
    float* W1r = Wr;
    float* W2r = Wr + HH*HH;
    float* Wcr = Wr + 2*HH*HH;
    float* Hc1 = Hc;
    float* Hc2 = Hc + (long)NSAMP*HH;

    cudaFuncSetAttribute(k_wgemm2<true>,  cudaFuncAttributeMaxDynamicSharedMemorySize, WG2_SMEM);
    cudaFuncSetAttribute(k_wgemm2<false>, cudaFuncAttributeMaxDynamicSharedMemorySize, WG2_SMEM);
    cudaFuncSetAttribute(k_costsink, cudaFuncAttributeMaxDynamicSharedMemorySize, CS_SMEM);
    cudaFuncSetAttribute(k_pcmp_w, cudaFuncAttributeMaxDynamicSharedMemorySize, PC_SMEM);

    // 0) round weights into scratch
    k_roundw<<<(2*HH*HH + 255)/256, 256>>>(W1, W2, Wc, Wr);
    // 1) embedding pool (enc rounded to tf32)
    k_embed<<<NSAMP, 320>>>(data, emb, enc);
    // 2) FFN (BK=32 pipeline, grid 237)
    dim3 gF(3, 79, 1);
    k_wgemm2<true><<<gF, 256, WG2_SMEM>>>(enc, W1r, b1, h1, nullptr,
                                          NSAMP, HH, DD, 0, 0, 1);
    k_wgemm2<true><<<gF, 256, WG2_SMEM>>>(h1, W2r, b2, henc, henct,
                                          NSAMP, HH, HH, 0, 0, 0);

    // fork: Hc GEMM on side stream
    cudaEventRecord(g_hx.eHenc, 0);
    cudaStreamWaitEvent(g_hx.sB, g_hx.eHenc, 0);
    dim3 gHc(3, 79, 2);
    k_wgemm2<false><<<gHc, 256, WG2_SMEM, g_hx.sB>>>(henct, Wcr, nullptr, Hc, nullptr,
                                                     NSAMP, HH, HH, (long)HH*HH,
                                                     (long)NSAMP*HH, 2);
    cudaEventRecord(g_hx.eHc, g_hx.sB);

    // chain A: fused WMMA cost + masked exp + Sinkhorn
    k_invnorm<<<(NSAMP + 7)/8, 256>>>(henc, invh);
    k_costsink<<<BB, 256, CS_SMEM>>>(henct, invh, row_idx, col_idx,
                                     row_len, col_len, Pb);

    // join: pcmp (R13 best config)
    cudaStreamWaitEvent(0, g_hx.eHc, 0);
    k_pcmp_w<<<dim3(2, 2, BB), 320, PC_SMEM>>>(Pb, Hc1, Hc2, bc, row_idx, col_idx,
                                               row_len, col_len, cr, cc);
    k_cls<<<BB, 320>>>(cr, cc, Wcls, bcls, Wout, bout, out);
}

// round 17
// speedup vs baseline: 1.0308x; 1.0298x over previous
#include <cuda_runtime.h>
#include <math.h>
#include <mma.h>
using namespace nvcuda;

// ---- problem dims ----
#define NSAMP 10000
#define LTOK  32
#define DD    300
#define HH    300
#define BB    256
#define NMX   128
#define ITERS 50

// ---- scratch ----
__device__ float g_enc [NSAMP*DD];
__device__ float g_h1  [NSAMP*HH];
__device__ float g_henc[NSAMP*HH];
__device__ float g_henct[NSAMP*HH];
__device__ float g_Hc  [2*NSAMP*HH];
__device__ float g_Wr  [4*HH*HH];
__device__ float g_invh[NSAMP];
__device__ float g_Pmat[BB*NMX*NMX];
__device__ float g_cr  [BB*HH];
__device__ float g_cc  [BB*HH];

// ---- streams/events (static init, pre-checkpoint) ----
struct HxStreams {
    cudaStream_t sB;
    cudaEvent_t eFork, eHenc, eHc, eW;
    HxStreams() {
        cudaStreamCreateWithFlags(&sB, cudaStreamNonBlocking);
        cudaEventCreateWithFlags(&eFork, cudaEventDisableTiming);
        cudaEventCreateWithFlags(&eHenc, cudaEventDisableTiming);
        cudaEventCreateWithFlags(&eHc,   cudaEventDisableTiming);
        cudaEventCreateWithFlags(&eW,    cudaEventDisableTiming);
    }
};
static HxStreams g_hx;

// ---- cp.async helpers ----
__device__ __forceinline__ void cpa16(unsigned int dst, const void* src) {
    asm volatile("cp.async.ca.shared.global [%0], [%1], 16;" :: "r"(dst), "l"(src));
}
__device__ __forceinline__ void cpa_commit() {
    asm volatile("cp.async.commit_group;");
}
template<int NN> __device__ __forceinline__ void cpa_wait() {
    asm volatile("cp.async.wait_group %0;" :: "n"(NN));
}

__device__ __forceinline__ float tf32r(float x) { return wmma::__float_to_tf32(x); }
__device__ __forceinline__ float4 tf32r4(float4 v) {
    v.x = tf32r(v.x); v.y = tf32r(v.y); v.z = tf32r(v.z); v.w = tf32r(v.w);
    return v;
}

// ============================================================
// 0) pre-round weights to tf32 (RN) into scratch
// ============================================================
__global__ void k_roundw(const float* __restrict__ W1, const float* __restrict__ W2,
                         const float* __restrict__ Wc, float* __restrict__ Wr) {
    int i = blockIdx.x * 256 + threadIdx.x;
    if (i < HH*HH)   Wr[i]           = tf32r(W1[i]);
    if (i < HH*HH)   Wr[HH*HH + i]   = tf32r(W2[i]);
    if (i < 2*HH*HH) Wr[2*HH*HH + i] = tf32r(Wc[i]);
}

// ============================================================
// 1) embedding + masked mean pool (output rounded to tf32)
// ============================================================
__global__ void k_embed(const int* __restrict__ data,
                        const float* __restrict__ emb,
                        float* __restrict__ enc) {
    int s = blockIdx.x;
    int t = threadIdx.x;            // 320 threads
    __shared__ int toks[LTOK];
    if (t < LTOK) toks[t] = data[s*LTOK + t];
    __syncthreads();
    int cnt = 0;
#pragma unroll
    for (int l = 0; l < LTOK; l++) cnt += (toks[l] != 0);
    float inv = 1.0f / (float)(cnt > 0 ? cnt : 1);
    if (t < DD) {
        float acc = 0.f;
#pragma unroll
        for (int l = 0; l < LTOK; l++) {
            int tok = toks[l];
            if (tok != 0) acc += emb[tok*DD + t];
        }
        enc[s*DD + t] = tf32r(acc * inv);
    }
}

// ============================================================
// 2) WMMA tf32 GEMM: 128x128, BK=16, 3-stage cp.async ring
//    (1 sync per k-tile), 256 thr / 8 warps (2m x 4n)
// ============================================================
#define SA    20
#define SB    132
#define SB2   164
#define ASTG  (128*SA)        // 2560
#define BSTG  (16*SB)         // 2112
#define BSTG2 (16*SB2)        // 2624
#define WSTG  (ASTG+BSTG)     // 4672 floats per stage
#define WG2_SMEM (3*WSTG*4)   // 56064 bytes

template<bool RELU>
__global__ void __launch_bounds__(256, 2)
k_wgemm2(const float* __restrict__ A, const float* __restrict__ B,
         const float* __restrict__ bias, float* __restrict__ C, float* __restrict__ C2,
         int M, int N, int K, long bStride, long cStride, int round_mask) {
    B += (long)blockIdx.z * bStride;
    C += (long)blockIdx.z * cStride;
    bool rnd = (round_mask >> blockIdx.z) & 1;
    extern __shared__ float sm[];
    unsigned int smb = (unsigned int)__cvta_generic_to_shared(sm);
    int t = threadIdx.x;
    int wid = t >> 5, wm = wid >> 2, wn = wid & 3;
    int mBase = blockIdx.y * 128, nBase = blockIdx.x * 128;
    int nT = (K + 15) >> 4;

    wmma::fragment<wmma::accumulator, 16, 16, 8, float> acc[4][2];
#pragma unroll
    for (int i = 0; i < 4; i++)
#pragma unroll
        for (int j = 0; j < 2; j++) wmma::fill_fragment(acc[i][j], 0.f);

#define W2_LOAD(k0, buf)                                                     \
    {                                                                        \
        int base = (buf)*WSTG;                                               \
        _Pragma("unroll")                                                    \
        for (int p = 0; p < 2; p++) {                                        \
            int id = t + p*256;                                              \
            int m = id >> 2, c4 = id & 3;                                    \
            int gm = mBase + m, gk = (k0) + c4*4;                            \
            int off = base + m*SA + c4*4;                                    \
            if (gm < M && gk < K) cpa16(smb + off*4, A + (size_t)gm*K + gk); \
            else *(float4*)(sm + off) = make_float4(0.f,0.f,0.f,0.f);        \
        }                                                                    \
        _Pragma("unroll")                                                    \
        for (int p = 0; p < 2; p++) {                                        \
            int id = t + p*256;                                              \
            int kr = id >> 5, n4 = id & 31;                                  \
            int gk = (k0) + kr, gn = nBase + n4*4;                           \
            int off = base + ASTG + kr*SB + n4*4;                            \
            if (gk < K && gn < N) cpa16(smb + off*4, B + (size_t)gk*N + gn); \
            else *(float4*)(sm + off) = make_float4(0.f,0.f,0.f,0.f);        \
        }                                                                    \
        cpa_commit();                                                        \
    }

    W2_LOAD(0, 0);
    if (nT > 1) W2_LOAD(16, 1);
    int buf = 0;
    for (int ti = 0; ti < nT; ti++) {
        if (ti + 1 < nT) cpa_wait<1>();
        else             cpa_wait<0>();
        __syncthreads();
        if (ti + 2 < nT) W2_LOAD((ti+2)*16, (ti+2)%3);
        const float* ap = sm + buf*WSTG;
        const float* bp = ap + ASTG;
#pragma unroll
        for (int ks = 0; ks < 2; ks++) {
            int k8 = ks*8;
            wmma::fragment<wmma::matrix_b, 16, 16, 8, wmma::precision::tf32, wmma::row_major> bf[2];
#pragma unroll
            for (int j = 0; j < 2; j++)
                wmma::load_matrix_sync(bf[j], bp + k8*SB + wn*32 + j*16, SB);
#pragma unroll
            for (int i = 0; i < 4; i++) {
                wmma::fragment<wmma::matrix_a, 16, 16, 8, wmma::precision::tf32, wmma::row_major> af;
                wmma::load_matrix_sync(af, ap + (wm*64 + i*16)*SA + k8, SA);
                wmma::mma_sync(acc[i][0], af, bf[0], acc[i][0]);
                wmma::mma_sync(acc[i][1], af, bf[1], acc[i][1]);
            }
        }
        buf = (buf + 1 == 3) ? 0 : buf + 1;
    }
#undef W2_LOAD
    __syncthreads();

#pragma unroll
    for (int ph = 0; ph < 2; ph++) {
        if (wm == ph) {
#pragma unroll
            for (int i = 0; i < 4; i++)
#pragma unroll
                for (int j = 0; j < 2; j++)
                    wmma::store_matrix_sync(sm + (i*16)*132 + wn*32 + j*16,
                                            acc[i][j], 132, wmma::mem_row_major);
        }
        __syncthreads();
#pragma unroll
        for (int q = 0; q < 8; q++) {
            int idx = t + q*256;
            int row = idx >> 5, c4 = idx & 31;
            int gm = mBase + ph*64 + row, gn = nBase + c4*4;
            if (gm < M && gn < N) {
                float4 v = *(float4*)&sm[row*132 + c4*4];
                float4 bb = bias ? *(const float4*)&bias[gn] : make_float4(0.f,0.f,0.f,0.f);
                v.x += bb.x; v.y += bb.y; v.z += bb.z; v.w += bb.w;
                if (RELU) {
                    v.x = fmaxf(v.x, 0.f); v.y = fmaxf(v.y, 0.f);
                    v.z = fmaxf(v.z, 0.f); v.w = fmaxf(v.w, 0.f);
                }
                if (C2) {
                    *(float4*)&C[(size_t)gm*N + gn] = v;
                    *(float4*)&C2[(size_t)gm*N + gn] = tf32r4(v);
                } else {
                    if (rnd) v = tf32r4(v);
                    *(float4*)&C[(size_t)gm*N + gn] = v;
                }
            }
        }
        __syncthreads();
    }
}

// ============================================================
// 3) per-sample inverse norm of henc (exact fp32)
// ============================================================
__global__ void k_invnorm(const float* __restrict__ henc, float* __restrict__ invh) {
    int s = blockIdx.x * 8 + (threadIdx.x >> 5);
    int l = threadIdx.x & 31;
    if (s >= NSAMP) return;
    const float4* hp = (const float4*)(henc + (size_t)s*HH);
    float sq = 0.f;
    for (int d4 = l; d4 < 75; d4 += 32) {
        float4 v = hp[d4];
        sq += v.x*v.x + v.y*v.y + v.z*v.z + v.w*v.w;
    }
#pragma unroll
    for (int o = 16; o; o >>= 1) sq += __shfl_down_sync(0xffffffffu, sq, o);
    if (l == 0) invh[s] = 1.0f / (sqrtf(sq) + 1e-8f);
}

// ============================================================
// 4) FUSED cost (WMMA tf32) + masked exp + Sinkhorn (2-stage)
// ============================================================
#define CS_KS   (128*132)
#define CS_AST  (128*20)
#define CS_SMEM ((CS_KS + 4*CS_AST)*4)   // 108544 bytes

__global__ void __launch_bounds__(256, 2)
k_costsink(const float* __restrict__ henct, const float* __restrict__ invh,
           const int* __restrict__ ridx, const int* __restrict__ cidx,
           const int* __restrict__ rlen, const int* __restrict__ clen,
           float* __restrict__ P) {
    int b = blockIdx.x;
    extern __shared__ float sm[];
    float* Ks  = sm;
    float* Ast = sm + CS_KS;
    float* Bst = Ast + 2*CS_AST;
    unsigned int smb = (unsigned int)__cvta_generic_to_shared(sm);
    __shared__ int sr[128], sc[128];
    __shared__ float sir[128], sic[128];
    int t = threadIdx.x;
    int wid = t >> 5, wm = wid >> 2, wn = wid & 3;
    if (t < 128) {
        int i = ridx[b*128 + t];
        sr[t] = i; sir[t] = invh[i];
    } else {
        int i = cidx[b*128 + (t-128)];
        sc[t-128] = i; sic[t-128] = invh[i];
    }
    __syncthreads();

    wmma::fragment<wmma::accumulator, 16, 16, 8, float> acc[4][2];
#pragma unroll
    for (int i = 0; i < 4; i++)
#pragma unroll
        for (int j = 0; j < 2; j++) wmma::fill_fragment(acc[i][j], 0.f);

#define CSW_LOAD(k0, buf)                                                    \
    {                                                                        \
        _Pragma("unroll")                                                    \
        for (int p = 0; p < 2; p++) {                                        \
            int id = t + p*256;                                              \
            int m = id >> 2, c4 = id & 3;                                    \
            int gk = (k0) + c4*4;                                            \
            int offA = CS_KS + (buf)*CS_AST + m*20 + c4*4;                   \
            int offB = CS_KS + 2*CS_AST + (buf)*CS_AST + m*20 + c4*4;        \
            if (gk < 300) {                                                  \
                cpa16(smb + offA*4, henct + (size_t)sr[m]*300 + gk);         \
                cpa16(smb + offB*4, henct + (size_t)sc[m]*300 + gk);         \
            } else {                                                         \
                *(float4*)(sm + offA) = make_float4(0.f,0.f,0.f,0.f);        \
                *(float4*)(sm + offB) = make_float4(0.f,0.f,0.f,0.f);        \
            }                                                                \
        }                                                                    \
        cpa_commit();                                                        \
    }

    CSW_LOAD(0, 0);
    for (int ti = 0; ti < 19; ti++) {
        int cur = ti & 1;
        if (ti + 1 < 19) { CSW_LOAD((ti+1)*16, cur^1); cpa_wait<1>(); }
        else             { cpa_wait<0>(); }
        __syncthreads();
        const float* ap = Ast + cur*CS_AST;
        const float* bp = Bst + cur*CS_AST;
#pragma unroll
        for (int ks = 0; ks < 2; ks++) {
            int k8 = ks*8;
            wmma::fragment<wmma::matrix_b, 16, 16, 8, wmma::precision::tf32, wmma::col_major> bf[2];
#pragma unroll
            for (int j = 0; j < 2; j++)
                wmma::load_matrix_sync(bf[j], bp + (wn*32 + j*16)*20 + k8, 20);
#pragma unroll
            for (int i = 0; i < 4; i++) {
                wmma::fragment<wmma::matrix_a, 16, 16, 8, wmma::precision::tf32, wmma::row_major> af;
                wmma::load_matrix_sync(af, ap + (wm*64 + i*16)*20 + k8, 20);
                wmma::mma_sync(acc[i][0], af, bf[0], acc[i][0]);
                wmma::mma_sync(acc[i][1], af, bf[1], acc[i][1]);
            }
        }
        __syncthreads();
    }
#undef CSW_LOAD

#pragma unroll
    for (int i = 0; i < 4; i++)
#pragma unroll
        for (int j = 0; j < 2; j++)
            wmma::store_matrix_sync(Ks + (wm*64 + i*16)*132 + wn*32 + j*16,
                                    acc[i][j], 132, wmma::mem_row_major);
    __syncthreads();

    int rl = rlen[b], cl = clen[b];
    int r128 = t & 127, half = t >> 7;
    float4 Kreg[16];
    if (r128 < rl) {
        float ir = sir[r128];
#pragma unroll
        for (int m4 = 0; m4 < 16; m4++) {
            int mm = half*64 + m4*4;
            float4 v4 = *(const float4*)&Ks[r128*132 + mm];
            v4.x = (mm+0 < cl) ? __expf((v4.x*ir*sic[mm+0] - 1.0f)*10.0f) : 0.f;
            v4.y = (mm+1 < cl) ? __expf((v4.y*ir*sic[mm+1] - 1.0f)*10.0f) : 0.f;
            v4.z = (mm+2 < cl) ? __expf((v4.z*ir*sic[mm+2] - 1.0f)*10.0f) : 0.f;
            v4.w = (mm+3 < cl) ? __expf((v4.w*ir*sic[mm+3] - 1.0f)*10.0f) : 0.f;
            Kreg[m4] = v4;
            *(float4*)&Ks[r128*132 + mm] = v4;
        }
    } else {
        float4 z4 = make_float4(0.f,0.f,0.f,0.f);
#pragma unroll
        for (int m4 = 0; m4 < 16; m4++) {
            Kreg[m4] = z4;
            *(float4*)&Ks[r128*132 + half*64 + m4*4] = z4;
        }
    }
    __syncthreads();

    float* u   = Ast;
    float* v   = Ast + 128;
    float* red = Ast + 256;
    float ra = 1.0f / (float)rl, rb = 1.0f / (float)cl;
    if (t < 128) u[t] = (t < cl) ? 1.0f : 0.0f;
    __syncthreads();

    int w8 = t >> 5, l32 = t & 31;
    const float4* u4h = (const float4*)(u + half*64);
    for (int it = 0; it < ITERS; it++) {
        float4 s4 = make_float4(0.f,0.f,0.f,0.f);
#pragma unroll
        for (int m = 0; m < 16; m++) {
            float4 uu = u4h[m];
            s4.x += Kreg[m].x*uu.x; s4.y += Kreg[m].y*uu.y;
            s4.z += Kreg[m].z*uu.z; s4.w += Kreg[m].w*uu.w;
        }
        red[half*128 + r128] = (s4.x + s4.y) + (s4.z + s4.w);
        __syncthreads();
        if (t < 128) {
            float s = red[t] + red[128 + t];
            v[t] = (t < rl) ? ra / s : 0.f;
        }
        __syncthreads();
        float4 q4 = make_float4(0.f,0.f,0.f,0.f);
#pragma unroll
        for (int rr = 0; rr < 16; rr++) {
            int n = w8*16 + rr;
            float vn = v[n];
            float4 k4 = *(const float4*)(Ks + n*132 + l32*4);
            q4.x += k4.x*vn; q4.y += k4.y*vn;
            q4.z += k4.z*vn; q4.w += k4.w*vn;
        }
        *(float4*)(red + w8*128 + l32*4) = q4;
        __syncthreads();
        if (t < 128) {
            float q = 0.f;
#pragma unroll
            for (int w = 0; w < 8; w++) q += red[w*128 + t];
            u[t] = (t < cl) ? rb / q : 0.f;
        }
        __syncthreads();
    }
    float ut = u[r128];
    float* Pb = P + (size_t)b*NMX*NMX;
    for (int i = half; i < 128; i += 2)
        Pb[i*128 + r128] = tf32r(v[i] * Ks[i*132 + r128] * ut);
}

// ============================================================
// 5) P-GEMM: 128x160 tiles, 320 thr, 3-stage ring + fused epilogue
// ============================================================
#define PASTG  2560
#define PSTG   (PASTG+BSTG2)     // 5184 floats per stage
#define PC_SMEM (3*PSTG*4)       // 62208 B (epilogue 64*164=10496 fits)

__global__ void __launch_bounds__(320, 2)
k_pcmp_w(const float* __restrict__ P,
         const float* __restrict__ Hc1, const float* __restrict__ Hc2,
         const float* __restrict__ bc,
         const int* __restrict__ ridx, const int* __restrict__ cidx,
         const int* __restrict__ rlen, const int* __restrict__ clen,
         float* __restrict__ cr, float* __restrict__ cc) {
    int b = blockIdx.z, mode = blockIdx.y;
    int hBase = blockIdx.x * 160;
    const int* gidxA = mode ? (ridx + b*128) : (cidx + b*128);
    const int* gidxE = mode ? (cidx + b*128) : (ridx + b*128);
    int len = mode ? clen[b] : rlen[b];
    const float* Pb = P + (size_t)b*NMX*NMX;

    extern __shared__ float sm[];
    unsigned int smb = (unsigned int)__cvta_generic_to_shared(sm);
    __shared__ int sA[128], sE[128];
    __shared__ float red2[320];
    int t = threadIdx.x;
    int wid = t >> 5;
    int wm = wid / 5, wn = wid % 5;
    if (t < 128) sA[t] = gidxA[t];
    else if (t < 256) sE[t-128] = gidxE[t-128];
    __syncthreads();

    wmma::fragment<wmma::accumulator, 16, 16, 8, float> acc[4][2];
#pragma unroll
    for (int i = 0; i < 4; i++)
#pragma unroll
        for (int j = 0; j < 2; j++) wmma::fill_fragment(acc[i][j], 0.f);

#define PCW_LOAD(k0, buf)                                                    \
    {                                                                        \
        int base = (buf)*PSTG;                                               \
        if (mode == 0) {                                                     \
            _Pragma("unroll")                                                \
            for (int p = 0; p < 2; p++) {                                    \
                int id = t + p*320;                                          \
                if (id < 512) {                                              \
                    int n = id >> 2, c4 = id & 3;                            \
                    int off = base + n*20 + c4*4;                            \
                    cpa16(smb + off*4, Pb + n*128 + (k0) + c4*4);            \
                }                                                            \
            }                                                                \
        } else {                                                             \
            _Pragma("unroll")                                                \
            for (int p = 0; p < 2; p++) {                                    \
                int id = t + p*320;                                          \
                if (id < 512) {                                              \
                    int kr = id >> 5, m4 = id & 31;                          \
                    int off = base + kr*132 + m4*4;                          \
                    cpa16(smb + off*4, Pb + ((k0) + kr)*128 + m4*4);         \
                }                                                            \
            }                                                                \
        }                                                                    \
        _Pragma("unroll")                                                    \
        for (int p = 0; p < 2; p++) {                                        \
            int id = t + p*320;                                              \
            int kr = id / 40, n4 = id % 40;                                  \
            int gh = hBase + n4*4;                                           \
            int off = base + PASTG + kr*SB2 + n4*4;                          \
            if (gh < 300) cpa16(smb + off*4, Hc2 + (size_t)sA[(k0)+kr]*300 + gh);\
            else *(float4*)(sm + off) = make_float4(0.f,0.f,0.f,0.f);        \
        }                                                                    \
        cpa_commit();                                                        \
    }

    PCW_LOAD(0, 0);
    PCW_LOAD(16, 1);
    int buf = 0;
    for (int ti = 0; ti < 8; ti++) {
        if (ti + 1 < 8) cpa_wait<1>();
        else            cpa_wait<0>();
        __syncthreads();
        if (ti + 2 < 8) PCW_LOAD((ti+2)*16, (ti+2)%3);
        const float* ap = sm + buf*PSTG;
        const float* bp = ap + PASTG;
#pragma unroll
        for (int ks = 0; ks < 2; ks++) {
            int k8 = ks*8;
            wmma::fragment<wmma::matrix_b, 16, 16, 8, wmma::precision::tf32, wmma::row_major> bf[2];
#pragma unroll
            for (int j = 0; j < 2; j++)
                wmma::load_matrix_sync(bf[j], bp + k8*SB2 + wn*32 + j*16, SB2);
            if (mode == 0) {
#pragma unroll
                for (int i = 0; i < 4; i++) {
                    wmma::fragment<wmma::matrix_a, 16, 16, 8, wmma::precision::tf32, wmma::row_major> af;
                    wmma::load_matrix_sync(af, ap + (wm*64 + i*16)*20 + k8, 20);
                    wmma::mma_sync(acc[i][0], af, bf[0], acc[i][0]);
                    wmma::mma_sync(acc[i][1], af, bf[1], acc[i][1]);
                }
            } else {
#pragma unroll
                for (int i = 0; i < 4; i++) {
                    wmma::fragment<wmma::matrix_a, 16, 16, 8, wmma::precision::tf32, wmma::col_major> af;
                    wmma::load_matrix_sync(af, ap + k8*132 + wm*64 + i*16, 132);
                    wmma::mma_sync(acc[i][0], af, bf[0], acc[i][0]);
                    wmma::mma_sync(acc[i][1], af, bf[1], acc[i][1]);
                }
            }
        }
        buf = (buf + 1 == 3) ? 0 : buf + 1;
    }
#undef PCW_LOAD
    __syncthreads();

    float colsum = 0.f;
    int hc = t % 160, rh = t / 160;
    int hg = hBase + hc;
    float bcv = (hg < 300) ? bc[hg] : 0.f;
#pragma unroll
    for (int ph = 0; ph < 2; ph++) {
        if (wm == ph) {
#pragma unroll
            for (int i = 0; i < 4; i++)
#pragma unroll
                for (int j = 0; j < 2; j++)
                    wmma::store_matrix_sync(sm + (i*16)*SB2 + wn*32 + j*16,
                                            acc[i][j], SB2, wmma::mem_row_major);
        }
        __syncthreads();
        if (hg < 300) {
            for (int r = rh*32; r < rh*32 + 32; r++) {
                int gr = ph*64 + r;
                if (gr < len)
                    colsum += fmaxf(sm[r*SB2 + hc] + Hc1[(size_t)sE[gr]*300 + hg] + bcv, 0.f);
            }
        }
        __syncthreads();
    }
    red2[t] = colsum;
    __syncthreads();
    if (t < 160 && hg < 300) {
        float* outp = mode ? cc : cr;
        outp[b*HH + hg] = red2[t] + red2[t + 160];
    }
}

// ============================================================
// 6) classifier head
// ============================================================
__global__ void k_cls(const float* __restrict__ cr,
                      const float* __restrict__ cc,
                      const float* __restrict__ Wcls,
                      const float* __restrict__ bcls,
                      const float* __restrict__ Wout,
                      const float* __restrict__ bout,
                      float* __restrict__ out) {
    int b = blockIdx.x;
    int t = threadIdx.x;              // 320 threads
    __shared__ float x[2*HH];
    for (int i = t; i < 2*HH; i += 320)
        x[i] = (i < HH) ? cr[b*HH + i] : cc[b*HH + i - HH];
    __syncthreads();
    float z = 0.f;
    if (t < HH) {
        float a0 = 0.f, a1 = 0.f, a2 = 0.f, a3 = 0.f;
#pragma unroll 4
        for (int k = 0; k < 2*HH; k += 4) {
            a0 += x[k+0]*Wcls[(k+0)*HH + t];
            a1 += x[k+1]*Wcls[(k+1)*HH + t];
            a2 += x[k+2]*Wcls[(k+2)*HH + t];
            a3 += x[k+3]*Wcls[(k+3)*HH + t];
        }
        z = fmaxf((a0+a1)+(a2+a3) + bcls[t], 0.f);
    }
    float s0 = (t < HH) ? z*Wout[t*2 + 0] : 0.f;
    float s1 = (t < HH) ? z*Wout[t*2 + 1] : 0.f;
#pragma unroll
    for (int o = 16; o; o >>= 1) {
        s0 += __shfl_down_sync(0xffffffffu, s0, o);
        s1 += __shfl_down_sync(0xffffffffu, s1, o);
    }
    __shared__ float r0[10], r1[10];
    if ((t & 31) == 0) { r0[t >> 5] = s0; r1[t >> 5] = s1; }
    __syncthreads();
    if (t == 0) {
        float a = 0.f, c = 0.f;
#pragma unroll
        for (int i = 0; i < 10; i++) { a += r0[i]; c += r1[i]; }
        out[b*2 + 0] = a + bout[0];
        out[b*2 + 1] = c + bout[1];
    }
}

// ============================================================
// launch
// ============================================================
extern "C" void kernel_launch(void* const* d_in, const int* in_sizes, int n_in,
                              void* d_out, int out_size) {
    const int*   data    = (const int*)  d_in[0];
    const int*   row_idx = (const int*)  d_in[1];
    const int*   col_idx = (const int*)  d_in[2];
    const int*   row_len = (const int*)  d_in[3];
    const int*   col_len = (const int*)  d_in[4];
    const float* emb     = (const float*)d_in[5];
    const float* W1      = (const float*)d_in[6];
    const float* b1      = (const float*)d_in[7];
    const float* W2      = (const float*)d_in[8];
    const float* b2      = (const float*)d_in[9];
    const float* Wc      = (const float*)d_in[10];
    const float* bc      = (const float*)d_in[11];
    const float* Wcls    = (const float*)d_in[12];
    const float* bcls    = (const float*)d_in[13];
    const float* Wout    = (const float*)d_in[14];
    const float* bout    = (const float*)d_in[15];
    float* out = (float*)d_out;

    float *enc, *h1, *henc, *henct, *Hc, *Wr, *invh, *Pb, *cr, *cc;
    cudaGetSymbolAddress((void**)&enc,   g_enc);
    cudaGetSymbolAddress((void**)&h1,    g_h1);
    cudaGetSymbolAddress((void**)&henc,  g_henc);
    cudaGetSymbolAddress((void**)&henct, g_henct);
    cudaGetSymbolAddress((void**)&Hc,    g_Hc);
    cudaGetSymbolAddress((void**)&Wr,    g_Wr);
    cudaGetSymbolAddress((void**)&invh,  g_invh);
    cudaGetSymbolAddress((void**)&Pb,    g_Pmat);
    cudaGetSymbolAddress((void**)&cr,    g_cr);
    cudaGetSymbolAddress((void**)&cc,    g_cc);
    float* W1r = Wr;
    float* W2r = Wr + HH*HH;
    float* Wcr = Wr + 2*HH*HH;
    float* Hc1 = Hc;
    float* Hc2 = Hc + (long)NSAMP*HH;

    cudaFuncSetAttribute(k_wgemm2<true>,  cudaFuncAttributeMaxDynamicSharedMemorySize, WG2_SMEM);
    cudaFuncSetAttribute(k_wgemm2<false>, cudaFuncAttributeMaxDynamicSharedMemorySize, WG2_SMEM);
    cudaFuncSetAttribute(k_costsink, cudaFuncAttributeMaxDynamicSharedMemorySize, CS_SMEM);
    cudaFuncSetAttribute(k_pcmp_w, cudaFuncAttributeMaxDynamicSharedMemorySize, PC_SMEM);

    // legal capture fork: record on capturing stream FIRST, then sB waits
    cudaEventRecord(g_hx.eFork, 0);
    cudaStreamWaitEvent(g_hx.sB, g_hx.eFork, 0);
    // 0) roundw on side stream, overlapped with embed
    k_roundw<<<(2*HH*HH + 255)/256, 256, 0, g_hx.sB>>>(W1, W2, Wc, Wr);
    cudaEventRecord(g_hx.eW, g_hx.sB);
    // 1) embedding pool (default stream, concurrent with roundw)
    k_embed<<<NSAMP, 320>>>(data, emb, enc);
    // 2) FFN (3-stage ring, BK=16)
    cudaStreamWaitEvent(0, g_hx.eW, 0);
    dim3 gF(3, 79, 1);
    k_wgemm2<true><<<gF, 256, WG2_SMEM>>>(enc, W1r, b1, h1, nullptr,
                                          NSAMP, HH, DD, 0, 0, 1);
    k_wgemm2<true><<<gF, 256, WG2_SMEM>>>(h1, W2r, b2, henc, henct,
                                          NSAMP, HH, HH, 0, 0, 0);

    // fork: Hc GEMM on side stream
    cudaEventRecord(g_hx.eHenc, 0);
    cudaStreamWaitEvent(g_hx.sB, g_hx.eHenc, 0);
    dim3 gHc(3, 79, 2);
    k_wgemm2<false><<<gHc, 256, WG2_SMEM, g_hx.sB>>>(henct, Wcr, nullptr, Hc, nullptr,
                                                     NSAMP, HH, HH, (long)HH*HH,
                                                     (long)NSAMP*HH, 2);
    cudaEventRecord(g_hx.eHc, g_hx.sB);

    // chain A: fused WMMA cost + masked exp + Sinkhorn
    k_invnorm<<<(NSAMP + 7)/8, 256>>>(henc, invh);
    k_costsink<<<BB, 256, CS_SMEM>>>(henct, invh, row_idx, col_idx,
                                     row_len, col_len, Pb);

    // join: pcmp (3-stage ring)
    cudaStreamWaitEvent(0, g_hx.eHc, 0);
    k_pcmp_w<<<dim3(2, 2, BB), 320, PC_SMEM>>>(Pb, Hc1, Hc2, bc, row_idx, col_idx,
                                               row_len, col_len, cr, cc);
    k_cls<<<BB, 320>>>(cr, cc, Wcls, bcls, Wout, bout, out);
}